// round 7
// baseline (speedup 1.0000x reference)
#include <cuda_runtime.h>
#include <cuda_bf16.h>
#include <cuda_fp16.h>
#include <cstdint>
#include <cstring>

// NT-Xent contrastive loss, sm_103 baseline ISA (mma.sync bf16 + ldmatrix + cp.async).
// Symmetric tiles (I<=J): row sums -> band I, col sums -> band J, u64 fixed-point
// atomics (deterministic). 3-stage B ring: ONE syncthreads per tile.

#define N2    8192
#define DD    128
#define NHALF 4096
#define RSTRIDE 272
#define TILE_SM (128 * RSTRIDE)          // 34816
#define SMEM_TOTAL (4 * TILE_SM)         // A + 3 B stages = 139264
#define FXS  68719476736.0f              // 2^36 (per-row exp sums)
#define FXL  1099511627776.0f            // 2^40 (loss terms)

__device__ __align__(16) __nv_bfloat16 g_znA[(size_t)N2 * DD];  // * 2*log2(e)
__device__ __align__(16) __nv_bfloat16 g_znB[(size_t)N2 * DD];
__device__ unsigned long long g_S[N2];
__device__ unsigned long long g_acc;
__device__ float g_pos[N2];
__device__ float g_diag[N2];

// ---------------- PTX helpers ----------------
__device__ __forceinline__ uint32_t smem_u32(const void* p) {
    uint32_t a;
    asm("{ .reg .u64 t; cvta.to.shared.u64 t, %1; cvt.u32.u64 %0, t; }" : "=r"(a) : "l"(p));
    return a;
}
__device__ __forceinline__ void cp16(uint32_t dst, const void* src) {
    asm volatile("cp.async.cg.shared.global [%0], [%1], 16;" :: "r"(dst), "l"(src));
}
#define CP_COMMIT() asm volatile("cp.async.commit_group;" ::: "memory")
#define CP_WAIT2()  asm volatile("cp.async.wait_group 2;" ::: "memory")
#define CP_WAIT1()  asm volatile("cp.async.wait_group 1;" ::: "memory")
#define CP_WAIT0()  asm volatile("cp.async.wait_group 0;" ::: "memory")

#define LDSM4(r0, r1, r2, r3, addr)                                              \
    asm volatile("ldmatrix.sync.aligned.m8n8.x4.shared.b16 {%0,%1,%2,%3}, [%4];" \
                 : "=r"(r0), "=r"(r1), "=r"(r2), "=r"(r3) : "r"(addr))

#define MMA16816(c, a, b0, b1)                                                 \
    asm volatile("mma.sync.aligned.m16n8k16.row.col.f32.bf16.bf16.f32 "        \
                 "{%0,%1,%2,%3}, {%4,%5,%6,%7}, {%8,%9}, {%0,%1,%2,%3};"       \
                 : "+f"((c)[0]), "+f"((c)[1]), "+f"((c)[2]), "+f"((c)[3])      \
                 : "r"((a)[0]), "r"((a)[1]), "r"((a)[2]), "r"((a)[3]),         \
                   "r"(b0), "r"(b1))

__device__ __forceinline__ float fast_lg2(float x) {
    float y; asm("lg2.approx.f32 %0, %1;" : "=f"(y) : "f"(x)); return y;
}

// ---------------- 1) prep ----------------
__global__ void prep_kernel(const float* __restrict__ zi, const float* __restrict__ zj) {
    int gtid = blockIdx.x * blockDim.x + threadIdx.x;
    if (gtid < N2) g_S[gtid] = 0ull;
    if (gtid == 0) g_acc = 0ull;
    int w    = gtid >> 5;
    int lane = threadIdx.x & 31;
    if (w >= NHALF) return;
    float4 a = reinterpret_cast<const float4*>(zi + (size_t)w * DD)[lane];
    float4 b = reinterpret_cast<const float4*>(zj + (size_t)w * DD)[lane];
    float sa = a.x * a.x + a.y * a.y + a.z * a.z + a.w * a.w;
    float sb = b.x * b.x + b.y * b.y + b.z * b.z + b.w * b.w;
    float dp = a.x * b.x + a.y * b.y + a.z * b.z + a.w * b.w;
#pragma unroll
    for (int o = 16; o > 0; o >>= 1) {
        sa += __shfl_xor_sync(0xffffffffu, sa, o);
        sb += __shfl_xor_sync(0xffffffffu, sb, o);
        dp += __shfl_xor_sync(0xffffffffu, dp, o);
    }
    float ia = rsqrtf(sa), ib = rsqrtf(sb);
    const float CA = 2.8853900817779268f;   // 2*log2(e)
    float iaC = ia * CA, ibC = ib * CA;

    __nv_bfloat16 sA[4], pA[4], sB[4], pB[4];
    sA[0]=__float2bfloat16_rn(a.x*iaC); sA[1]=__float2bfloat16_rn(a.y*iaC);
    sA[2]=__float2bfloat16_rn(a.z*iaC); sA[3]=__float2bfloat16_rn(a.w*iaC);
    pA[0]=__float2bfloat16_rn(a.x*ia);  pA[1]=__float2bfloat16_rn(a.y*ia);
    pA[2]=__float2bfloat16_rn(a.z*ia);  pA[3]=__float2bfloat16_rn(a.w*ia);
    sB[0]=__float2bfloat16_rn(b.x*ibC); sB[1]=__float2bfloat16_rn(b.y*ibC);
    sB[2]=__float2bfloat16_rn(b.z*ibC); sB[3]=__float2bfloat16_rn(b.w*ibC);
    pB[0]=__float2bfloat16_rn(b.x*ib);  pB[1]=__float2bfloat16_rn(b.y*ib);
    pB[2]=__float2bfloat16_rn(b.z*ib);  pB[3]=__float2bfloat16_rn(b.w*ib);

    float da = 0.f, db = 0.f;
#pragma unroll
    for (int k = 0; k < 4; ++k) {
        da += __bfloat162float(sA[k]) * __bfloat162float(pA[k]);
        db += __bfloat162float(sB[k]) * __bfloat162float(pB[k]);
    }
#pragma unroll
    for (int o = 16; o > 0; o >>= 1) {
        da += __shfl_xor_sync(0xffffffffu, da, o);
        db += __shfl_xor_sync(0xffffffffu, db, o);
    }
    if (lane == 0) {
        float p = 2.0f * dp * ia * ib;
        g_pos[w] = p; g_pos[w + NHALF] = p;
        g_diag[w]         = exp2f(da);
        g_diag[w + NHALF] = exp2f(db);
    }
    uint2 u;
    memcpy(&u, sA, 8); reinterpret_cast<uint2*>(g_znA + (size_t)w * DD)[lane] = u;
    memcpy(&u, pA, 8); reinterpret_cast<uint2*>(g_znB + (size_t)w * DD)[lane] = u;
    memcpy(&u, sB, 8); reinterpret_cast<uint2*>(g_znA + (size_t)(w + NHALF) * DD)[lane] = u;
    memcpy(&u, pB, 8); reinterpret_cast<uint2*>(g_znB + (size_t)(w + NHALF) * DD)[lane] = u;
}

// ---------------- 2) fused symmetric HMMA + exp2 row/col sums ----------------
__device__ __forceinline__ void load_tile(uint32_t dstBase, const __nv_bfloat16* src,
                                          int tid) {
#pragma unroll
    for (int p = 0; p < 8; ++p) {
        int id = p * 256 + tid;
        int row = id >> 4, ch = id & 15;
        cp16(dstBase + row * RSTRIDE + ch * 16,
             reinterpret_cast<const char*>(src) + row * 256 + ch * 16);
    }
}

__global__ __launch_bounds__(256, 1) void simlse_kernel() {
    extern __shared__ unsigned char smem[];
    const uint32_t sb   = smem_u32(smem);
    const uint32_t smA  = sb;
    const uint32_t smB0 = sb + TILE_SM;

    const int tid = threadIdx.x, wid = tid >> 5, lane = tid & 31;
    const int bi    = blockIdx.x >> 2;
    const int chunk = blockIdx.x & 3;
    const int wn = wid & 3, wm = wid >> 2;

    const uint32_t aOff = (uint32_t)(lane & 15) * RSTRIDE + (uint32_t)((lane >> 4) << 4);
    const uint32_t bOff = (uint32_t)((lane & 7) + ((lane & 16) ? 8 : 0)) * RSTRIDE +
                          (uint32_t)((lane & 8) ? 16 : 0);
    const __half2 zero2 = __float2half2_rn(0.f);

#pragma unroll 1
    for (int phase = 0; phase < 2; ++phase) {
        const int I = phase ? (63 - bi) : bi;
        const int nJ = (I + chunk <= 63) ? ((63 - I - chunk) / 4 + 1) : 0;
        if (nJ <= 0) continue;

        __syncthreads();   // all stage/A reads of previous phase complete
        load_tile(smA, g_znA + (size_t)I * 128 * DD, tid);
        CP_COMMIT();
        load_tile(smB0, g_znB + (size_t)(I + chunk) * 128 * DD, tid);
        CP_COMMIT();
        if (nJ > 1)
            load_tile(smB0 + TILE_SM, g_znB + (size_t)(I + chunk + 4) * 128 * DD, tid);
        CP_COMMIT();
        CP_WAIT2();        // A arrived (B0,B1 outstanding)
        __syncthreads();

        uint32_t afr[4][8][4];
        {
            const uint32_t aBase = smA + (uint32_t)(wm * 64) * RSTRIDE + aOff;
#pragma unroll
            for (int mb = 0; mb < 4; ++mb)
#pragma unroll
                for (int ks = 0; ks < 8; ++ks)
                    LDSM4(afr[mb][ks][0], afr[mb][ks][1], afr[mb][ks][2], afr[mb][ks][3],
                          aBase + (uint32_t)(mb * 16) * RSTRIDE + (uint32_t)(ks * 32));
        }

        float frow[4][2] = {{0.f,0.f},{0.f,0.f},{0.f,0.f},{0.f,0.f}};

#pragma unroll 1
        for (int t = 0; t < nJ; ++t) {
            const int J = I + chunk + 4 * t;
            const int s = t % 3;
            CP_WAIT1();
            __syncthreads();     // stage s visible; stage (t+2)%3 reads (tile t-1) done
            if (t + 2 < nJ)
                load_tile(smB0 + (uint32_t)((t + 2) % 3) * TILE_SM,
                          g_znB + (size_t)(J + 8) * 128 * DD, tid);
            CP_COMMIT();

            __half2 cs[2][2] = {{zero2, zero2}, {zero2, zero2}};
            __half2 sum01[4] = {zero2, zero2, zero2, zero2};
            __half2 sum23[4] = {zero2, zero2, zero2, zero2};
#pragma unroll
            for (int np = 0; np < 2; ++np) {
                const uint32_t bBase = smB0 + (uint32_t)s * TILE_SM +
                                       (uint32_t)(wn * 32 + np * 16) * RSTRIDE + bOff;
                uint32_t bfr[8][4];
#pragma unroll
                for (int ks = 0; ks < 8; ++ks)
                    LDSM4(bfr[ks][0], bfr[ks][1], bfr[ks][2], bfr[ks][3],
                          bBase + (uint32_t)(ks * 32));

                float acc[4][2][4];
#pragma unroll
                for (int mb = 0; mb < 4; ++mb)
#pragma unroll
                    for (int nb = 0; nb < 2; ++nb)
#pragma unroll
                        for (int r = 0; r < 4; ++r) acc[mb][nb][r] = 0.f;
#pragma unroll
                for (int ks = 0; ks < 8; ++ks)
#pragma unroll
                    for (int mb = 0; mb < 4; ++mb) {
                        MMA16816(acc[mb][0], afr[mb][ks], bfr[ks][0], bfr[ks][1]);
                        MMA16816(acc[mb][1], afr[mb][ks], bfr[ks][2], bfr[ks][3]);
                    }
#pragma unroll
                for (int mb = 0; mb < 4; ++mb)
#pragma unroll
                    for (int nb = 0; nb < 2; ++nb) {
                        __half2 e01 = h2exp2(__floats2half2_rn(acc[mb][nb][0], acc[mb][nb][1]));
                        __half2 e23 = h2exp2(__floats2half2_rn(acc[mb][nb][2], acc[mb][nb][3]));
                        sum01[mb] = __hadd2(sum01[mb], e01);
                        sum23[mb] = __hadd2(sum23[mb], e23);
                        cs[np][nb] = __hadd2(cs[np][nb], __hadd2(e01, e23));
                    }
            }
            // rows -> fp32 register accumulators
#pragma unroll
            for (int mb = 0; mb < 4; ++mb) {
                float2 f0 = __half22float2(sum01[mb]);
                float2 f1 = __half22float2(sum23[mb]);
                frow[mb][0] += f0.x + f0.y;
                frow[mb][1] += f1.x + f1.y;
            }
            // cols: shuffle-reduce over row groups, direct u64 atomics (no smem/sync)
            if (J != I) {
#pragma unroll
                for (int np = 0; np < 2; ++np)
#pragma unroll
                    for (int nb = 0; nb < 2; ++nb) {
                        __half2 v = cs[np][nb];
                        v = __hadd2(v, __shfl_xor_sync(0xffffffffu, v, 4));
                        v = __hadd2(v, __shfl_xor_sync(0xffffffffu, v, 8));
                        v = __hadd2(v, __shfl_xor_sync(0xffffffffu, v, 16));
                        if (lane < 4) {
                            float2 f = __half22float2(v);
                            int c = J * 128 + wn * 32 + np * 16 + nb * 8 + lane * 2;
                            atomicAdd(&g_S[c + 0], __float2ull_rn(f.x * FXS));
                            atomicAdd(&g_S[c + 1], __float2ull_rn(f.y * FXS));
                        }
                    }
            }
        }

        // ---- row-sum flush for band I: quad reduce + direct atomics ----
#pragma unroll
        for (int mb = 0; mb < 4; ++mb)
#pragma unroll
            for (int h = 0; h < 2; ++h) {
                frow[mb][h] += __shfl_xor_sync(0xffffffffu, frow[mb][h], 1);
                frow[mb][h] += __shfl_xor_sync(0xffffffffu, frow[mb][h], 2);
            }
        if ((lane & 3) == 0) {
            int q = lane >> 2;
            int rbase = I * 128 + wm * 64 + q;
#pragma unroll
            for (int mb = 0; mb < 4; ++mb) {
                atomicAdd(&g_S[rbase + mb * 16 + 0], __float2ull_rn(frow[mb][0] * FXS));
                atomicAdd(&g_S[rbase + mb * 16 + 8], __float2ull_rn(frow[mb][1] * FXS));
            }
        }
    }
    CP_WAIT0();   // drain async copies before exit
}

// ---------------- 3) finish ----------------
__global__ void finish1_kernel() {
    const int i = blockIdx.x * blockDim.x + threadIdx.x;
    const int lane = threadIdx.x & 31;
    const float LN2 = 0.6931471805599453f;
    const float INV = 1.0f / FXS;
    float S = __ull2float_rn(g_S[i]) * INV;
    float term = fast_lg2(S - g_diag[i]) * LN2 - g_pos[i];
    unsigned long long fx = __float2ull_rn(term * FXL);
#pragma unroll
    for (int o = 16; o > 0; o >>= 1)
        fx += __shfl_xor_sync(0xffffffffu, fx, o);
    if (lane == 0) atomicAdd(&g_acc, fx);
}
__global__ void finish2_kernel(float* __restrict__ out) {
    out[0] = (float)((double)g_acc * (1.0 / 1099511627776.0) / (double)N2);
}

// ---------------- launch ----------------
extern "C" void kernel_launch(void* const* d_in, const int* in_sizes, int n_in,
                              void* d_out, int out_size) {
    const float* zi = (const float*)d_in[0];
    const float* zj = (const float*)d_in[1];
    cudaFuncSetAttribute(simlse_kernel, cudaFuncAttributeMaxDynamicSharedMemorySize,
                         SMEM_TOTAL);
    prep_kernel<<<NHALF / 8, 256>>>(zi, zj);
    simlse_kernel<<<128, 256, SMEM_TOTAL>>>();
    finish1_kernel<<<N2 / 512, 512>>>();
    finish2_kernel<<<1, 1>>>((float*)d_out);
}

// round 8
// speedup vs baseline: 1.2012x; 1.2012x over previous
#include <cuda_runtime.h>
#include <cuda_bf16.h>
#include <cuda_fp16.h>
#include <cstdint>
#include <cstring>

// NT-Xent contrastive loss, sm_103 baseline ISA (mma.sync bf16 + ldmatrix + cp.async).
// Symmetric tiles (I<=J); row sums -> band I, col sums -> band J (u64 fixed point,
// deterministic). WIDE WINDOWS: 2 J-tiles per barrier pair (half the sync per MMA).

#define N2    8192
#define DD    128
#define NHALF 4096
#define RSTRIDE 272
#define TILE_SM (128 * RSTRIDE)          // 34816
#define WIN_SM  (2 * TILE_SM)            // 69632 (2 tiles per stage)
#define SM_COLRED (TILE_SM + 2 * WIN_SM) // 174080
#define SMEM_TOTAL (SM_COLRED + 2048)    // 176128
#define FXS  68719476736.0f              // 2^36

__device__ __align__(16) __nv_bfloat16 g_znA[(size_t)N2 * DD];  // * 2*log2(e)
__device__ __align__(16) __nv_bfloat16 g_znB[(size_t)N2 * DD];
__device__ unsigned long long g_S[N2];
__device__ float g_pos[N2];
__device__ float g_diag[N2];

// ---------------- PTX helpers ----------------
__device__ __forceinline__ uint32_t smem_u32(const void* p) {
    uint32_t a;
    asm("{ .reg .u64 t; cvta.to.shared.u64 t, %1; cvt.u32.u64 %0, t; }" : "=r"(a) : "l"(p));
    return a;
}
__device__ __forceinline__ void cp16(uint32_t dst, const void* src) {
    asm volatile("cp.async.cg.shared.global [%0], [%1], 16;" :: "r"(dst), "l"(src));
}
#define CP_COMMIT() asm volatile("cp.async.commit_group;" ::: "memory")
#define CP_WAIT1()  asm volatile("cp.async.wait_group 1;" ::: "memory")
#define CP_WAIT0()  asm volatile("cp.async.wait_group 0;" ::: "memory")

#define LDSM4(r0, r1, r2, r3, addr)                                              \
    asm volatile("ldmatrix.sync.aligned.m8n8.x4.shared.b16 {%0,%1,%2,%3}, [%4];" \
                 : "=r"(r0), "=r"(r1), "=r"(r2), "=r"(r3) : "r"(addr))

#define MMA16816(c, a, b0, b1)                                                 \
    asm volatile("mma.sync.aligned.m16n8k16.row.col.f32.bf16.bf16.f32 "        \
                 "{%0,%1,%2,%3}, {%4,%5,%6,%7}, {%8,%9}, {%0,%1,%2,%3};"       \
                 : "+f"((c)[0]), "+f"((c)[1]), "+f"((c)[2]), "+f"((c)[3])      \
                 : "r"((a)[0]), "r"((a)[1]), "r"((a)[2]), "r"((a)[3]),         \
                   "r"(b0), "r"(b1))

__device__ __forceinline__ float fast_lg2(float x) {
    float y; asm("lg2.approx.f32 %0, %1;" : "=f"(y) : "f"(x)); return y;
}

// ---------------- 1) prep ----------------
__global__ void prep_kernel(const float* __restrict__ zi, const float* __restrict__ zj) {
    int gtid = blockIdx.x * blockDim.x + threadIdx.x;
    if (gtid < N2) g_S[gtid] = 0ull;
    int w    = gtid >> 5;
    int lane = threadIdx.x & 31;
    if (w >= NHALF) return;
    float4 a = reinterpret_cast<const float4*>(zi + (size_t)w * DD)[lane];
    float4 b = reinterpret_cast<const float4*>(zj + (size_t)w * DD)[lane];
    float sa = a.x * a.x + a.y * a.y + a.z * a.z + a.w * a.w;
    float sb = b.x * b.x + b.y * b.y + b.z * b.z + b.w * b.w;
    float dp = a.x * b.x + a.y * b.y + a.z * b.z + a.w * b.w;
#pragma unroll
    for (int o = 16; o > 0; o >>= 1) {
        sa += __shfl_xor_sync(0xffffffffu, sa, o);
        sb += __shfl_xor_sync(0xffffffffu, sb, o);
        dp += __shfl_xor_sync(0xffffffffu, dp, o);
    }
    float ia = rsqrtf(sa), ib = rsqrtf(sb);
    const float CA = 2.8853900817779268f;   // 2*log2(e)
    float iaC = ia * CA, ibC = ib * CA;

    __nv_bfloat16 sA[4], pA[4], sB[4], pB[4];
    sA[0]=__float2bfloat16_rn(a.x*iaC); sA[1]=__float2bfloat16_rn(a.y*iaC);
    sA[2]=__float2bfloat16_rn(a.z*iaC); sA[3]=__float2bfloat16_rn(a.w*iaC);
    pA[0]=__float2bfloat16_rn(a.x*ia);  pA[1]=__float2bfloat16_rn(a.y*ia);
    pA[2]=__float2bfloat16_rn(a.z*ia);  pA[3]=__float2bfloat16_rn(a.w*ia);
    sB[0]=__float2bfloat16_rn(b.x*ibC); sB[1]=__float2bfloat16_rn(b.y*ibC);
    sB[2]=__float2bfloat16_rn(b.z*ibC); sB[3]=__float2bfloat16_rn(b.w*ibC);
    pB[0]=__float2bfloat16_rn(b.x*ib);  pB[1]=__float2bfloat16_rn(b.y*ib);
    pB[2]=__float2bfloat16_rn(b.z*ib);  pB[3]=__float2bfloat16_rn(b.w*ib);

    float da = 0.f, db = 0.f;
#pragma unroll
    for (int k = 0; k < 4; ++k) {
        da += __bfloat162float(sA[k]) * __bfloat162float(pA[k]);
        db += __bfloat162float(sB[k]) * __bfloat162float(pB[k]);
    }
#pragma unroll
    for (int o = 16; o > 0; o >>= 1) {
        da += __shfl_xor_sync(0xffffffffu, da, o);
        db += __shfl_xor_sync(0xffffffffu, db, o);
    }
    if (lane == 0) {
        float p = 2.0f * dp * ia * ib;
        g_pos[w] = p; g_pos[w + NHALF] = p;
        g_diag[w]         = exp2f(da);
        g_diag[w + NHALF] = exp2f(db);
    }
    uint2 u;
    memcpy(&u, sA, 8); reinterpret_cast<uint2*>(g_znA + (size_t)w * DD)[lane] = u;
    memcpy(&u, pA, 8); reinterpret_cast<uint2*>(g_znB + (size_t)w * DD)[lane] = u;
    memcpy(&u, sB, 8); reinterpret_cast<uint2*>(g_znA + (size_t)(w + NHALF) * DD)[lane] = u;
    memcpy(&u, pB, 8); reinterpret_cast<uint2*>(g_znB + (size_t)(w + NHALF) * DD)[lane] = u;
}

// ---------------- 2) fused symmetric HMMA + exp2 row/col sums ----------------
__device__ __forceinline__ void load_tile(uint32_t dstBase, const __nv_bfloat16* src,
                                          int tid) {
#pragma unroll
    for (int p = 0; p < 8; ++p) {
        int id = p * 256 + tid;
        int row = id >> 4, ch = id & 15;
        cp16(dstBase + row * RSTRIDE + ch * 16,
             reinterpret_cast<const char*>(src) + row * 256 + ch * 16);
    }
}

__global__ __launch_bounds__(256, 1) void simlse_kernel() {
    extern __shared__ unsigned char smem[];
    const uint32_t sb   = smem_u32(smem);
    const uint32_t smA  = sb;
    const uint32_t smST = sb + TILE_SM;                 // 2 stages of WIN_SM
    float* colred = reinterpret_cast<float*>(smem + SM_COLRED);  // [2 J][2 wm][128]

    const int tid = threadIdx.x, wid = tid >> 5, lane = tid & 31;
    const int bi    = blockIdx.x >> 2;
    const int chunk = blockIdx.x & 3;
    const int wn = wid & 3, wm = wid >> 2;

    const uint32_t aOff = (uint32_t)(lane & 15) * RSTRIDE + (uint32_t)((lane >> 4) << 4);
    const uint32_t bOff = (uint32_t)((lane & 7) + ((lane & 16) ? 8 : 0)) * RSTRIDE +
                          (uint32_t)((lane & 8) ? 16 : 0);
    const __half2 zero2 = __float2half2_rn(0.f);

#pragma unroll 1
    for (int phase = 0; phase < 2; ++phase) {
        const int I = phase ? (63 - bi) : bi;
        const int nJ = (I + chunk <= 63) ? ((63 - I - chunk) / 4 + 1) : 0;
        if (nJ <= 0) continue;
        const int nW = (nJ + 1) >> 1;

        __syncthreads();   // previous phase reads of smA/stages complete
        load_tile(smA, g_znA + (size_t)I * 128 * DD, tid);
        CP_COMMIT();
        {
            int Ja = I + chunk;
            int Jb = (nJ > 1) ? Ja + 4 : 63;   // dummy band if single tile
            load_tile(smST,           g_znB + (size_t)Ja * 128 * DD, tid);
            load_tile(smST + TILE_SM, g_znB + (size_t)Jb * 128 * DD, tid);
            CP_COMMIT();
        }
        CP_WAIT1();        // A arrived
        __syncthreads();

        uint32_t afr[4][8][4];
        {
            const uint32_t aBase = smA + (uint32_t)(wm * 64) * RSTRIDE + aOff;
#pragma unroll
            for (int mb = 0; mb < 4; ++mb)
#pragma unroll
                for (int ks = 0; ks < 8; ++ks)
                    LDSM4(afr[mb][ks][0], afr[mb][ks][1], afr[mb][ks][2], afr[mb][ks][3],
                          aBase + (uint32_t)(mb * 16) * RSTRIDE + (uint32_t)(ks * 32));
        }

        float frow[4][2] = {{0.f,0.f},{0.f,0.f},{0.f,0.f},{0.f,0.f}};

#pragma unroll 1
        for (int u = 0; u < nW; ++u) {
            const uint32_t stage = smST + (uint32_t)(u & 1) * WIN_SM;
            const int J1 = I + chunk + 8 * u;
            const bool v2 = (2 * u + 1) < nJ;
            const int J2 = J1 + 4;

            CP_WAIT0();       // window u resident
            __syncthreads();  // stage visible to all; prev stage reads done
            if (u + 1 < nW) {
                int t1 = 2 * (u + 1);
                int Ja = I + chunk + 4 * t1;
                int Jb = (t1 + 1 < nJ) ? Ja + 4 : 63;
                uint32_t nst = smST + (uint32_t)((u + 1) & 1) * WIN_SM;
                load_tile(nst,           g_znB + (size_t)Ja * 128 * DD, tid);
                load_tile(nst + TILE_SM, g_znB + (size_t)Jb * 128 * DD, tid);
            }
            CP_COMMIT();

#pragma unroll 1
            for (int tt = 0; tt < 2; ++tt) {
                if (tt == 1 && !v2) break;
                __half2 cs[2][2] = {{zero2, zero2}, {zero2, zero2}};
                __half2 sum01[4] = {zero2, zero2, zero2, zero2};
                __half2 sum23[4] = {zero2, zero2, zero2, zero2};
#pragma unroll
                for (int np = 0; np < 2; ++np) {
                    const uint32_t bBase = stage + (uint32_t)tt * TILE_SM +
                                           (uint32_t)(wn * 32 + np * 16) * RSTRIDE + bOff;
                    uint32_t bfr[8][4];
#pragma unroll
                    for (int ks = 0; ks < 8; ++ks)
                        LDSM4(bfr[ks][0], bfr[ks][1], bfr[ks][2], bfr[ks][3],
                              bBase + (uint32_t)(ks * 32));

                    float acc[4][2][4];
#pragma unroll
                    for (int mb = 0; mb < 4; ++mb)
#pragma unroll
                        for (int nb = 0; nb < 2; ++nb)
#pragma unroll
                            for (int r = 0; r < 4; ++r) acc[mb][nb][r] = 0.f;
#pragma unroll
                    for (int ks = 0; ks < 8; ++ks)
#pragma unroll
                        for (int mb = 0; mb < 4; ++mb) {
                            MMA16816(acc[mb][0], afr[mb][ks], bfr[ks][0], bfr[ks][1]);
                            MMA16816(acc[mb][1], afr[mb][ks], bfr[ks][2], bfr[ks][3]);
                        }
#pragma unroll
                    for (int mb = 0; mb < 4; ++mb)
#pragma unroll
                        for (int nb = 0; nb < 2; ++nb) {
                            __half2 e01 = h2exp2(__floats2half2_rn(acc[mb][nb][0], acc[mb][nb][1]));
                            __half2 e23 = h2exp2(__floats2half2_rn(acc[mb][nb][2], acc[mb][nb][3]));
                            sum01[mb] = __hadd2(sum01[mb], e01);
                            sum23[mb] = __hadd2(sum23[mb], e23);
                            cs[np][nb] = __hadd2(cs[np][nb], __hadd2(e01, e23));
                        }
                }
                // rows -> fp32
#pragma unroll
                for (int mb = 0; mb < 4; ++mb) {
                    float2 f0 = __half22float2(sum01[mb]);
                    float2 f1 = __half22float2(sum23[mb]);
                    frow[mb][0] += f0.x + f0.y;
                    frow[mb][1] += f1.x + f1.y;
                }
                // cols -> colred[tt]
#pragma unroll
                for (int np = 0; np < 2; ++np)
#pragma unroll
                    for (int nb = 0; nb < 2; ++nb) {
                        __half2 v = cs[np][nb];
                        v = __hadd2(v, __shfl_xor_sync(0xffffffffu, v, 4));
                        v = __hadd2(v, __shfl_xor_sync(0xffffffffu, v, 8));
                        v = __hadd2(v, __shfl_xor_sync(0xffffffffu, v, 16));
                        if (lane < 4) {
                            float2 f = __half22float2(v);
                            int c = wn * 32 + np * 16 + nb * 8 + lane * 2;
                            colred[tt * 256 + wm * 128 + c + 0] = f.x;
                            colred[tt * 256 + wm * 128 + c + 1] = f.y;
                        }
                    }
            }
            __syncthreads();   // colred ready; stage reads complete
            {
                int jsub = tid >> 7, c = tid & 127;
                int Jx = jsub ? J2 : J1;
                bool doit = jsub ? v2 : (J1 != I);
                if (doit) {
                    float v = colred[jsub * 256 + c] + colred[jsub * 256 + 128 + c];
                    atomicAdd(&g_S[Jx * 128 + c], __float2ull_rn(v * FXS));
                }
            }
        }

        // ---- row flush for band I (once per phase, direct atomics) ----
#pragma unroll
        for (int mb = 0; mb < 4; ++mb)
#pragma unroll
            for (int h = 0; h < 2; ++h) {
                frow[mb][h] += __shfl_xor_sync(0xffffffffu, frow[mb][h], 1);
                frow[mb][h] += __shfl_xor_sync(0xffffffffu, frow[mb][h], 2);
            }
        if ((lane & 3) == 0) {
            int q = lane >> 2;
            int rbase = I * 128 + wm * 64 + q;
#pragma unroll
            for (int mb = 0; mb < 4; ++mb) {
                atomicAdd(&g_S[rbase + mb * 16 + 0], __float2ull_rn(frow[mb][0] * FXS));
                atomicAdd(&g_S[rbase + mb * 16 + 8], __float2ull_rn(frow[mb][1] * FXS));
            }
        }
    }
    CP_WAIT0();
}

// ---------------- 3) finish ----------------
__global__ void finish_kernel(float* __restrict__ out) {
    __shared__ float red[32];
    const int t = threadIdx.x, lane = t & 31, w = t >> 5;
    const float LN2 = 0.6931471805599453f;
    const float INV = 1.0f / FXS;
    float s = 0.f;
#pragma unroll
    for (int u = 0; u < 8; ++u) {
        int i = t + u * 1024;
        float S = __ull2float_rn(g_S[i]) * INV;
        s += fast_lg2(S - g_diag[i]) * LN2 - g_pos[i];
    }
#pragma unroll
    for (int o = 16; o > 0; o >>= 1) s += __shfl_xor_sync(0xffffffffu, s, o);
    if (lane == 0) red[w] = s;
    __syncthreads();
    if (w == 0) {
        float v = red[lane];
#pragma unroll
        for (int o = 16; o > 0; o >>= 1) v += __shfl_xor_sync(0xffffffffu, v, o);
        if (lane == 0) out[0] = v * (1.0f / (float)N2);
    }
}

// ---------------- launch ----------------
extern "C" void kernel_launch(void* const* d_in, const int* in_sizes, int n_in,
                              void* d_out, int out_size) {
    const float* zi = (const float*)d_in[0];
    const float* zj = (const float*)d_in[1];
    cudaFuncSetAttribute(simlse_kernel, cudaFuncAttributeMaxDynamicSharedMemorySize,
                         SMEM_TOTAL);
    prep_kernel<<<NHALF / 8, 256>>>(zi, zj);
    simlse_kernel<<<128, 256, SMEM_TOTAL>>>();
    finish_kernel<<<1, 1024>>>((float*)d_out);
}

// round 10
// speedup vs baseline: 1.2020x; 1.0007x over previous
#include <cuda_runtime.h>
#include <cuda_fp16.h>
#include <cstdint>
#include <cstring>

// NT-Xent contrastive loss, sm_103 baseline ISA. fp16 HMMA with f16 accumulators.
//   g_znA = normalize(z) * 2*log2(e) (fp16) -> MMA acc directly = log2-domain arg
//   g_znB = normalize(z) (fp16)
// Symmetric tiles (I<=J): row sums -> band I, col sums -> band J, u64 fixed-point
// atomics (deterministic). loss = mean( ln(S_i - diag_i) - pos_i ).

#define N2    8192
#define DD    128
#define NHALF 4096
#define RSTRIDE 272
#define TILE_SM (128 * RSTRIDE)          // 34816
#define SM_COLRED (4 * TILE_SM)          // A + 3 B stages before colred
#define SMEM_TOTAL (4 * TILE_SM + 1024)  // 140288
#define FXS  68719476736.0f              // 2^36 (exp-sum fixed point)
#define FXL  1099511627776.0f            // 2^40 (loss-term fixed point)

__device__ __align__(16) __half g_znA[(size_t)N2 * DD];
__device__ __align__(16) __half g_znB[(size_t)N2 * DD];
__device__ unsigned long long g_S[N2];
__device__ unsigned long long g_acc;
__device__ unsigned int g_tick;
__device__ float g_pos[N2];
__device__ float g_diag[N2];

// ---------------- PTX helpers ----------------
__device__ __forceinline__ uint32_t smem_u32(const void* p) {
    uint32_t a;
    asm("{ .reg .u64 t; cvta.to.shared.u64 t, %1; cvt.u32.u64 %0, t; }" : "=r"(a) : "l"(p));
    return a;
}
__device__ __forceinline__ void cp16(uint32_t dst, const void* src) {
    asm volatile("cp.async.cg.shared.global [%0], [%1], 16;" :: "r"(dst), "l"(src));
}
#define CP_COMMIT() asm volatile("cp.async.commit_group;" ::: "memory")
#define CP_WAIT2()  asm volatile("cp.async.wait_group 2;" ::: "memory")
#define CP_WAIT1()  asm volatile("cp.async.wait_group 1;" ::: "memory")
#define CP_WAIT0()  asm volatile("cp.async.wait_group 0;" ::: "memory")

#define LDSM4(r0, r1, r2, r3, addr)                                              \
    asm volatile("ldmatrix.sync.aligned.m8n8.x4.shared.b16 {%0,%1,%2,%3}, [%4];" \
                 : "=r"(r0), "=r"(r1), "=r"(r2), "=r"(r3) : "r"(addr))

// f16 accumulators: D = {2 regs of f16x2}. c[0]=row r cols (c,c+1); c[1]=row r+8.
#define MMA16816H(c, a, b0, b1)                                                \
    asm volatile("mma.sync.aligned.m16n8k16.row.col.f16.f16.f16.f16 "          \
                 "{%0,%1}, {%2,%3,%4,%5}, {%6,%7}, {%0,%1};"                   \
                 : "+r"((c)[0]), "+r"((c)[1])                                  \
                 : "r"((a)[0]), "r"((a)[1]), "r"((a)[2]), "r"((a)[3]),         \
                   "r"(b0), "r"(b1))

__device__ __forceinline__ float fast_lg2(float x) {
    float y; asm("lg2.approx.f32 %0, %1;" : "=f"(y) : "f"(x)); return y;
}
__device__ __forceinline__ __half2 u2h2(uint32_t u) {
    __half2 h; memcpy(&h, &u, 4); return h;
}

// ---------------- 1) prep ----------------
__global__ void prep_kernel(const float* __restrict__ zi, const float* __restrict__ zj) {
    int gtid = blockIdx.x * blockDim.x + threadIdx.x;
    if (gtid < N2) g_S[gtid] = 0ull;
    if (gtid == 0) { g_acc = 0ull; g_tick = 0u; }
    int w    = gtid >> 5;
    int lane = threadIdx.x & 31;
    if (w >= NHALF) return;
    float4 a = reinterpret_cast<const float4*>(zi + (size_t)w * DD)[lane];
    float4 b = reinterpret_cast<const float4*>(zj + (size_t)w * DD)[lane];
    float sa = a.x * a.x + a.y * a.y + a.z * a.z + a.w * a.w;
    float sb = b.x * b.x + b.y * b.y + b.z * b.z + b.w * b.w;
    float dp = a.x * b.x + a.y * b.y + a.z * b.z + a.w * b.w;
#pragma unroll
    for (int o = 16; o > 0; o >>= 1) {
        sa += __shfl_xor_sync(0xffffffffu, sa, o);
        sb += __shfl_xor_sync(0xffffffffu, sb, o);
        dp += __shfl_xor_sync(0xffffffffu, dp, o);
    }
    float ia = rsqrtf(sa), ib = rsqrtf(sb);
    const float CA = 2.8853900817779268f;   // 2*log2(e)
    float iaC = ia * CA, ibC = ib * CA;

    __half sA[4], pA[4], sB[4], pB[4];
    sA[0]=__float2half_rn(a.x*iaC); sA[1]=__float2half_rn(a.y*iaC);
    sA[2]=__float2half_rn(a.z*iaC); sA[3]=__float2half_rn(a.w*iaC);
    pA[0]=__float2half_rn(a.x*ia);  pA[1]=__float2half_rn(a.y*ia);
    pA[2]=__float2half_rn(a.z*ia);  pA[3]=__float2half_rn(a.w*ia);
    sB[0]=__float2half_rn(b.x*ibC); sB[1]=__float2half_rn(b.y*ibC);
    sB[2]=__float2half_rn(b.z*ibC); sB[3]=__float2half_rn(b.w*ibC);
    pB[0]=__float2half_rn(b.x*ib);  pB[1]=__float2half_rn(b.y*ib);
    pB[2]=__float2half_rn(b.z*ib);  pB[3]=__float2half_rn(b.w*ib);

    // self-dot of quantized values (approximates the MMA's diagonal term)
    float da = 0.f, db = 0.f;
#pragma unroll
    for (int k = 0; k < 4; ++k) {
        da += __half2float(sA[k]) * __half2float(pA[k]);
        db += __half2float(sB[k]) * __half2float(pB[k]);
    }
#pragma unroll
    for (int o = 16; o > 0; o >>= 1) {
        da += __shfl_xor_sync(0xffffffffu, da, o);
        db += __shfl_xor_sync(0xffffffffu, db, o);
    }
    if (lane == 0) {
        float p = 2.0f * dp * ia * ib;
        g_pos[w] = p; g_pos[w + NHALF] = p;
        g_diag[w]         = exp2f(da);
        g_diag[w + NHALF] = exp2f(db);
    }
    uint2 u;
    memcpy(&u, sA, 8); reinterpret_cast<uint2*>(g_znA + (size_t)w * DD)[lane] = u;
    memcpy(&u, pA, 8); reinterpret_cast<uint2*>(g_znB + (size_t)w * DD)[lane] = u;
    memcpy(&u, sB, 8); reinterpret_cast<uint2*>(g_znA + (size_t)(w + NHALF) * DD)[lane] = u;
    memcpy(&u, pB, 8); reinterpret_cast<uint2*>(g_znB + (size_t)(w + NHALF) * DD)[lane] = u;
}

// ---------------- 2) fused symmetric HMMA(f16 acc) + exp2 row/col sums ----------------
__device__ __forceinline__ void load_tile(uint32_t dstBase, const __half* src, int tid) {
#pragma unroll
    for (int p = 0; p < 8; ++p) {
        int id = p * 256 + tid;
        int row = id >> 4, ch = id & 15;
        cp16(dstBase + row * RSTRIDE + ch * 16,
             reinterpret_cast<const char*>(src) + row * 256 + ch * 16);
    }
}

__global__ __launch_bounds__(256, 1) void simlse_kernel() {
    extern __shared__ unsigned char smem[];
    const uint32_t sb   = smem_u32(smem);
    const uint32_t smA  = sb;
    const uint32_t smB0 = sb + TILE_SM;                          // 3 stages
    float* colred = reinterpret_cast<float*>(smem + SM_COLRED);  // [2 wm][128]

    const int tid = threadIdx.x, wid = tid >> 5, lane = tid & 31;
    const int bi    = blockIdx.x >> 2;
    const int chunk = blockIdx.x & 3;
    const int wn = wid & 3, wm = wid >> 2;

    const uint32_t aOff = (uint32_t)(lane & 15) * RSTRIDE + (uint32_t)((lane >> 4) << 4);
    const uint32_t bOff = (uint32_t)((lane & 7) + ((lane & 16) ? 8 : 0)) * RSTRIDE +
                          (uint32_t)((lane & 8) ? 16 : 0);
    const __half2 zero2 = __float2half2_rn(0.f);

#pragma unroll 1
    for (int phase = 0; phase < 2; ++phase) {
        const int I = phase ? (63 - bi) : bi;
        const int nJ = (I + chunk <= 63) ? ((63 - I - chunk) / 4 + 1) : 0;
        if (nJ <= 0) continue;

        __syncthreads();   // previous-phase reads complete
        load_tile(smA, g_znA + (size_t)I * 128 * DD, tid);
        CP_COMMIT();
        load_tile(smB0, g_znB + (size_t)(I + chunk) * 128 * DD, tid);
        CP_COMMIT();
        if (nJ > 1)
            load_tile(smB0 + TILE_SM, g_znB + (size_t)(I + chunk + 4) * 128 * DD, tid);
        CP_COMMIT();
        CP_WAIT2();
        __syncthreads();

        uint32_t afr[4][8][4];
        {
            const uint32_t aBase = smA + (uint32_t)(wm * 64) * RSTRIDE + aOff;
#pragma unroll
            for (int mb = 0; mb < 4; ++mb)
#pragma unroll
                for (int ks = 0; ks < 8; ++ks)
                    LDSM4(afr[mb][ks][0], afr[mb][ks][1], afr[mb][ks][2], afr[mb][ks][3],
                          aBase + (uint32_t)(mb * 16) * RSTRIDE + (uint32_t)(ks * 32));
        }

        float frow[4][2] = {{0.f,0.f},{0.f,0.f},{0.f,0.f},{0.f,0.f}};

#pragma unroll 1
        for (int t = 0; t < nJ; ++t) {
            const int J = I + chunk + 4 * t;
            const int s = t % 3;
            CP_WAIT1();
            __syncthreads();
            if (t + 2 < nJ)
                load_tile(smB0 + (uint32_t)((t + 2) % 3) * TILE_SM,
                          g_znB + (size_t)(J + 8) * 128 * DD, tid);
            CP_COMMIT();

            __half2 cs[2][2] = {{zero2, zero2}, {zero2, zero2}};
            __half2 sumr0[4] = {zero2, zero2, zero2, zero2};   // rows r    (col pair)
            __half2 sumr8[4] = {zero2, zero2, zero2, zero2};   // rows r+8
#pragma unroll
            for (int np = 0; np < 2; ++np) {
                const uint32_t bBase = smB0 + (uint32_t)s * TILE_SM +
                                       (uint32_t)(wn * 32 + np * 16) * RSTRIDE + bOff;
                uint32_t bfr[8][4];
#pragma unroll
                for (int ks = 0; ks < 8; ++ks)
                    LDSM4(bfr[ks][0], bfr[ks][1], bfr[ks][2], bfr[ks][3],
                          bBase + (uint32_t)(ks * 32));

                uint32_t acc[4][2][2];
#pragma unroll
                for (int mb = 0; mb < 4; ++mb)
#pragma unroll
                    for (int nb = 0; nb < 2; ++nb) { acc[mb][nb][0] = 0u; acc[mb][nb][1] = 0u; }
#pragma unroll
                for (int ks = 0; ks < 8; ++ks)
#pragma unroll
                    for (int mb = 0; mb < 4; ++mb) {
                        MMA16816H(acc[mb][0], afr[mb][ks], bfr[ks][0], bfr[ks][1]);
                        MMA16816H(acc[mb][1], afr[mb][ks], bfr[ks][2], bfr[ks][3]);
                    }
#pragma unroll
                for (int mb = 0; mb < 4; ++mb)
#pragma unroll
                    for (int nb = 0; nb < 2; ++nb) {
                        __half2 e0 = h2exp2(u2h2(acc[mb][nb][0]));   // row r,   cols (c,c+1)
                        __half2 e1 = h2exp2(u2h2(acc[mb][nb][1]));   // row r+8, cols (c,c+1)
                        sumr0[mb] = __hadd2(sumr0[mb], e0);
                        sumr8[mb] = __hadd2(sumr8[mb], e1);
                        cs[np][nb] = __hadd2(cs[np][nb], __hadd2(e0, e1));
                    }
            }
            // rows -> fp32 accumulators (per-tile flush keeps fp16 sums small)
#pragma unroll
            for (int mb = 0; mb < 4; ++mb) {
                float2 f0 = __half22float2(sumr0[mb]);
                float2 f1 = __half22float2(sumr8[mb]);
                frow[mb][0] += f0.x + f0.y;
                frow[mb][1] += f1.x + f1.y;
            }
            // cols: reduce over row groups (xor 4,8,16); lanes 0..3 publish col pairs
#pragma unroll
            for (int np = 0; np < 2; ++np)
#pragma unroll
                for (int nb = 0; nb < 2; ++nb) {
                    __half2 v = cs[np][nb];
                    v = __hadd2(v, __shfl_xor_sync(0xffffffffu, v, 4));
                    v = __hadd2(v, __shfl_xor_sync(0xffffffffu, v, 8));
                    v = __hadd2(v, __shfl_xor_sync(0xffffffffu, v, 16));
                    if (lane < 4) {
                        float2 f = __half22float2(v);
                        int c = wn * 32 + np * 16 + nb * 8 + lane * 2;
                        colred[wm * 128 + c + 0] = f.x;
                        colred[wm * 128 + c + 1] = f.y;
                    }
                }
            __syncthreads();   // colred ready; stage-s reads complete
            if (J != I && tid < 128) {
                float v = colred[tid] + colred[128 + tid];
                atomicAdd(&g_S[J * 128 + tid], __float2ull_rn(v * FXS));
            }
        }

        // ---- row flush for band I (quad reduce + direct atomics) ----
#pragma unroll
        for (int mb = 0; mb < 4; ++mb)
#pragma unroll
            for (int h = 0; h < 2; ++h) {
                frow[mb][h] += __shfl_xor_sync(0xffffffffu, frow[mb][h], 1);
                frow[mb][h] += __shfl_xor_sync(0xffffffffu, frow[mb][h], 2);
            }
        if ((lane & 3) == 0) {
            int q = lane >> 2;
            int rbase = I * 128 + wm * 64 + q;
#pragma unroll
            for (int mb = 0; mb < 4; ++mb) {
                atomicAdd(&g_S[rbase + mb * 16 + 0], __float2ull_rn(frow[mb][0] * FXS));
                atomicAdd(&g_S[rbase + mb * 16 + 8], __float2ull_rn(frow[mb][1] * FXS));
            }
        }
    }
    CP_WAIT0();
}

// ---------------- 3) finish: 8 blocks, last block writes ----------------
__global__ void finish_kernel(float* __restrict__ out) {
    const int t = threadIdx.x;
    const int i = blockIdx.x * 1024 + t;
    const float LN2 = 0.6931471805599453f;
    float S = __ull2float_rn(g_S[i]) * (1.0f / FXS);
    float term = fast_lg2(S - g_diag[i]) * LN2 - g_pos[i];   // term > 0 always
    unsigned long long fx = __float2ull_rn(term * FXL);
#pragma unroll
    for (int o = 16; o > 0; o >>= 1)
        fx += __shfl_xor_sync(0xffffffffu, fx, o);
    if ((t & 31) == 0) atomicAdd(&g_acc, fx);
    __threadfence();
    __syncthreads();
    if (t == 0) {
        unsigned int tk = atomicAdd(&g_tick, 1u);
        if (tk == gridDim.x - 1) {
            __threadfence();
            unsigned long long total = atomicAdd(&g_acc, 0ull);
            out[0] = (float)((double)total * (1.0 / 1099511627776.0) / (double)N2);
        }
    }
}

// ---------------- launch ----------------
extern "C" void kernel_launch(void* const* d_in, const int* in_sizes, int n_in,
                              void* d_out, int out_size) {
    const float* zi = (const float*)d_in[0];
    const float* zj = (const float*)d_in[1];
    cudaFuncSetAttribute(simlse_kernel, cudaFuncAttributeMaxDynamicSharedMemorySize,
                         SMEM_TOTAL);
    prep_kernel<<<NHALF / 8, 256>>>(zi, zj);
    simlse_kernel<<<128, 256, SMEM_TOTAL>>>();
    finish_kernel<<<N2 / 1024, 1024>>>((float*)d_out);
}